// round 4
// baseline (speedup 1.0000x reference)
#include <cuda_runtime.h>
#include <math.h>

// Problem constants (shapes fixed by the dataset)
#define NPTS  14
#define NEDGE 13          // N-1
#define NF1   3           // dim-1 features
#define BMAX  65536
#define FDIM  512
#define H1    64
#define H2    32
#define NSEG  (H1 + 1)    // 65 piecewise segments
#define SROW  33          // padded row stride for segment tables (scalar reads)
#define BIGF  1e30f

// ---------------- scratch (static device globals; no allocation) ----------------
__device__ float g_deaths0[NEDGE * BMAX];   // MST deaths, [it][b] (coalesced over b)
__device__ float g_dmax[BMAX];              // per-batch max distance
__device__ float g_p0[BMAX];                // deaths0[1]-deaths0[0] per batch
__device__ float g_p1b[BMAX];               // births1[1]-births1[0]
__device__ float g_p1d[BMAX];               // deaths1[1]-deaths1[0]
__device__ float g_S[2];                    // entropy denominators
__device__ float g_h2sum[2 * H2];           // [0:32] diag0 h2 sum, [32:64] diag1 h2 sum
__device__ float g_bp[H1];                  // sorted breakpoints (x=0 path)
__device__ float g_A[NSEG * H2];            // piecewise slope table
__device__ float g_C[NSEG * H2];            // piecewise offset table (b2 baked in)

// ---------------- init ----------------
__global__ void k_init(float* ent_slot) {
    int t = threadIdx.x;
    if (t < 2)  g_S[t] = 0.f;
    if (t < 64) g_h2sum[t] = 0.f;
    if (t == 0) *ent_slot = 0.f;
}

// ---------------- breakpoints via rank sort (shared mem only, no local arrays) ----
__global__ void k_bp(const float* __restrict__ W1, const float* __restrict__ b1) {
    __shared__ float st[H1];
    int j = threadIdx.x;   // 0..63
    float w = W1[H1 + j];
    float t = (w != 0.f) ? (-b1[j] / w) : __int_as_float(0x7f800000);
    st[j] = t;
    __syncthreads();
    int r = 0;
#pragma unroll
    for (int i = 0; i < H1; i++) {
        float ti = st[i];
        r += (ti < t || (ti == t && i < j)) ? 1 : 0;
    }
    g_bp[r] = t;
}

// ---------------- per-segment linear tables: h2pre_k(d) = A[s][k]*d + C[s][k] ------
__global__ void k_table(const float* __restrict__ W1, const float* __restrict__ b1,
                        const float* __restrict__ W2, const float* __restrict__ b2) {
    int s = blockIdx.x;     // 0..NSEG-1
    int k = threadIdx.x;    // 0..H2-1
    const float INF = __int_as_float(0x7f800000);
    float lo = (s == 0)  ? -INF : g_bp[s - 1];
    float hi = (s == H1) ?  INF : g_bp[s];
    float rep;
    bool li = isinf(lo), hiinf = isinf(hi);
    if (li && hiinf)      rep = 0.f;
    else if (li)          rep = hi - 1.f;
    else if (hiinf)       rep = lo + 1.f;
    else                  rep = 0.5f * (lo + hi);
    float A = 0.f, C = b2[k];
    for (int j = 0; j < H1; j++) {
        float w = W1[H1 + j], bb = b1[j];
        bool act = (w == 0.f) ? (bb > 0.f) : ((w * rep + bb) > 0.f);
        if (act) {
            float m = W2[j * H2 + k];
            A += w * m;
            C += bb * m;
        }
    }
    g_A[s * H2 + k] = A;
    g_C[s * H2 + k] = C;
}

// ---------------- MST (Prim on squared distances) + dmax + entropy terms + euler ----
__global__ void __launch_bounds__(128)
k_mst(const float* __restrict__ pc, const float* __restrict__ rb,
      const float* __restrict__ rd, float* __restrict__ euler, int B) {
    int b = blockIdx.x * blockDim.x + threadIdx.x;
    float s0 = 0.f, s1 = 0.f;
    if (b < B) {
        const float* p = pc + (long long)b * (NPTS * 3);
        float px[NPTS], py[NPTS], pz[NPTS];
#pragma unroll
        for (int i = 0; i < NPTS; i++) {
            px[i] = p[3 * i]; py[i] = p[3 * i + 1]; pz[i] = p[3 * i + 2];
        }
        float key[NPTS];
        float dmax2 = 0.f;
        key[0] = BIGF;
#pragma unroll
        for (int i = 1; i < NPTS; i++) {
            float dx = px[i] - px[0], dy = py[i] - py[0], dz = pz[i] - pz[0];
            float d2 = dx * dx + dy * dy + dz * dz;
            key[i] = d2;
            dmax2 = fmaxf(dmax2, d2);
        }
        float m1 = BIGF, m2 = BIGF;          // two smallest MST weights (squared)
#pragma unroll 1
        for (int it = 0; it < NEDGE; it++) {
            float bv = key[0]; int bj = 0;
#pragma unroll
            for (int j = 1; j < NPTS; j++) {
                if (key[j] < bv) { bv = key[j]; bj = j; }
            }
            if (bv < m1) { m2 = m1; m1 = bv; } else if (bv < m2) { m2 = bv; }
            g_deaths0[it * B + b] = sqrtf(fmaxf(bv, 1e-24f));   // coalesced over b
            float qx = px[0], qy = py[0], qz = pz[0];
#pragma unroll
            for (int c = 1; c < NPTS; c++) {
                if (bj == c) { qx = px[c]; qy = py[c]; qz = pz[c]; }
            }
#pragma unroll
            for (int i = 1; i < NPTS; i++) {
                float dx = px[i] - qx, dy = py[i] - qy, dz = pz[i] - qz;
                float d2 = dx * dx + dy * dy + dz * dz;
                dmax2 = fmaxf(dmax2, d2);
                float nk = fminf(key[i], d2);
                key[i] = (i == bj || key[i] >= BIGF) ? BIGF : nk;
            }
        }
        float dmax = sqrtf(fmaxf(dmax2, 1e-24f));
        g_dmax[b] = dmax;
        float d0 = sqrtf(fmaxf(m1, 1e-24f));
        float d1 = sqrtf(fmaxf(m2, 1e-24f));
        float p0 = d1 - d0;
        g_p0[b] = p0;
        if (p0 > 0.f) s0 = p0;
        float p1b = (rb[b * NF1 + 1] - rb[b * NF1 + 0]) * dmax * 0.3f;
        float p1d = p1b + (rd[b * NF1 + 1] - rd[b * NF1 + 0]) * dmax * 0.4f;
        g_p1b[b] = p1b;
        g_p1d[b] = p1d;
        if (p1b > 0.f) s1 += p1b;
        if (p1d > 0.f) s1 += p1d;
        euler[b] = (float)(NEDGE - NF1);
    }
    // block reduce entropy denominators
    __shared__ float s_e[2][4];
    int lane = threadIdx.x & 31, wid = threadIdx.x >> 5;
    int nw = blockDim.x >> 5;
#pragma unroll
    for (int o = 16; o; o >>= 1) {
        s0 += __shfl_xor_sync(0xffffffffu, s0, o);
        s1 += __shfl_xor_sync(0xffffffffu, s1, o);
    }
    if (lane == 0) { s_e[0][wid] = s0; s_e[1][wid] = s1; }
    __syncthreads();
    if (wid == 0 && lane < 2) {
        float v = 0.f;
        for (int w = 0; w < nw; w++) v += s_e[lane][w];
        atomicAdd(&g_S[lane], v);
    }
}

// ---------------- diag0 h2 sum via piecewise tables (k-chunked, low regs) ----------
__global__ void __launch_bounds__(256)
k_diag0(int total) {
    __shared__ float sbp[H1];
    __shared__ float sA[NSEG * SROW];
    __shared__ float sC[NSEG * SROW];
    __shared__ float s_part[8][H2];
    for (int i = threadIdx.x; i < H1; i += blockDim.x) sbp[i] = g_bp[i];
    for (int i = threadIdx.x; i < NSEG * H2; i += blockDim.x) {
        int s = i >> 5, k = i & 31;
        sA[s * SROW + k] = g_A[i];
        sC[s * SROW + k] = g_C[i];
    }
    __syncthreads();
    int lane = threadIdx.x & 31, wid = threadIdx.x >> 5;
    int nw = blockDim.x >> 5;
    int stride = gridDim.x * blockDim.x;
#pragma unroll 1
    for (int chunk = 0; chunk < 2; chunk++) {
        float acc[16];
#pragma unroll
        for (int k = 0; k < 16; k++) acc[k] = 0.f;
        for (int i = blockIdx.x * blockDim.x + threadIdx.x; i < total; i += stride) {
            float d = g_deaths0[i];
            int lo = 0, hi = H1;
#pragma unroll
            for (int s = 0; s < 6; s++) {
                int mid = (lo + hi) >> 1;
                if (sbp[mid] < d) lo = mid + 1; else hi = mid;
            }
            const float* Ar = sA + lo * SROW + chunk * 16;
            const float* Cr = sC + lo * SROW + chunk * 16;
#pragma unroll
            for (int k = 0; k < 16; k++)
                acc[k] += fmaxf(fmaf(Ar[k], d, Cr[k]), 0.f);
        }
#pragma unroll
        for (int k = 0; k < 16; k++) {
            float v = acc[k];
#pragma unroll
            for (int o = 16; o; o >>= 1) v += __shfl_xor_sync(0xffffffffu, v, o);
            if (lane == 0) s_part[wid][chunk * 16 + k] = v;
        }
    }
    __syncthreads();
    if (threadIdx.x < H2) {
        float v = 0.f;
        for (int w = 0; w < nw; w++) v += s_part[w][threadIdx.x];
        atomicAdd(&g_h2sum[threadIdx.x], v);
    }
}

// ---------------- diag1 h2 sum via 2->64->32 MLP (kc/jc-chunked, low regs) --------
__global__ void __launch_bounds__(256)
k_diag1(const float* __restrict__ W1, const float* __restrict__ b1,
        const float* __restrict__ W2, const float* __restrict__ b2,
        const float* __restrict__ rb, const float* __restrict__ rd, int B) {
    __shared__ __align__(16) float sw[H1 * 4];       // (W1[0,j], W1[1,j], b1[j], 0)
    __shared__ __align__(16) float sW2t[H2 * H1];    // W2 transposed: [k][j]
    __shared__ float sb2[H2];
    __shared__ float s_part[8][H2];
    for (int j = threadIdx.x; j < H1; j += blockDim.x) {
        sw[j * 4 + 0] = W1[j];
        sw[j * 4 + 1] = W1[H1 + j];
        sw[j * 4 + 2] = b1[j];
        sw[j * 4 + 3] = 0.f;
    }
    for (int i = threadIdx.x; i < H1 * H2; i += blockDim.x) {
        int j = i / H2, k = i % H2;
        sW2t[k * H1 + j] = W2[i];
    }
    if (threadIdx.x < H2) sb2[threadIdx.x] = b2[threadIdx.x];
    __syncthreads();

    int lane = threadIdx.x & 31, wid = threadIdx.x >> 5;
    int nw = blockDim.x >> 5;
    int total = NF1 * B;
    int stride = gridDim.x * blockDim.x;
#pragma unroll 1
    for (int kc = 0; kc < 2; kc++) {
        float acc[16];
#pragma unroll
        for (int k = 0; k < 16; k++) acc[k] = 0.f;
        for (int i = blockIdx.x * blockDim.x + threadIdx.x; i < total; i += stride) {
            float dm = g_dmax[i / NF1];
            float x = rb[i] * dm * 0.3f;
            float y = fmaf(rd[i] * dm, 0.4f, x);
            float t[16];
#pragma unroll
            for (int k = 0; k < 16; k++) t[k] = sb2[kc * 16 + k];
#pragma unroll
            for (int jc = 0; jc < 4; jc++) {
                float h1[16];
#pragma unroll
                for (int j = 0; j < 16; j++) {
                    float4 w = ((const float4*)sw)[jc * 16 + j];
                    h1[j] = fmaxf(fmaf(x, w.x, fmaf(y, w.y, w.z)), 0.f);
                }
#pragma unroll
                for (int k = 0; k < 16; k++) {
                    const float4* wv = (const float4*)(sW2t + (kc * 16 + k) * H1 + jc * 16);
                    float s = t[k];
#pragma unroll
                    for (int j4 = 0; j4 < 4; j4++) {
                        float4 w = wv[j4];
                        s = fmaf(h1[j4 * 4 + 0], w.x,
                            fmaf(h1[j4 * 4 + 1], w.y,
                            fmaf(h1[j4 * 4 + 2], w.z,
                            fmaf(h1[j4 * 4 + 3], w.w, s))));
                    }
                    t[k] = s;
                }
            }
#pragma unroll
            for (int k = 0; k < 16; k++) acc[k] += fmaxf(t[k], 0.f);
        }
#pragma unroll
        for (int k = 0; k < 16; k++) {
            float v = acc[k];
#pragma unroll
            for (int o = 16; o; o >>= 1) v += __shfl_xor_sync(0xffffffffu, v, o);
            if (lane == 0) s_part[wid][kc * 16 + k] = v;
        }
    }
    __syncthreads();
    if (threadIdx.x < H2) {
        float v = 0.f;
        for (int w = 0; w < nw; w++) v += s_part[w][threadIdx.x];
        atomicAdd(&g_h2sum[H2 + threadIdx.x], v);
    }
}

// ---------------- features: (mean_h2_0 + mean_h2_1) @ W3 + 2*b3 ----------------
__global__ void k_feat(const float* __restrict__ W3, const float* __restrict__ b3,
                       float* __restrict__ out, int B) {
    __shared__ float u[H2];
    if (threadIdx.x < H2) {
        int k = threadIdx.x;
        u[k] = g_h2sum[k] / ((float)NEDGE * (float)B)
             + g_h2sum[H2 + k] / ((float)NF1 * (float)B);
    }
    __syncthreads();
    int f = threadIdx.x;
    if (f < FDIM) {
        float t = 2.f * b3[f];
#pragma unroll
        for (int k = 0; k < H2; k++) t += u[k] * W3[k * FDIM + f];
        out[f] = t;
    }
}

// ---------------- entropy pass 2 ----------------
__global__ void __launch_bounds__(256)
k_entropy(float* __restrict__ ent, int B) {
    int b = blockIdx.x * blockDim.x + threadIdx.x;
    float t = 0.f;
    if (b < B) {
        float S0 = fmaxf(g_S[0], 1e-30f), S1 = fmaxf(g_S[1], 1e-30f);
        float p = g_p0[b];
        if (p > 0.f)  { float q = p  / S0; t -= q * logf(q + 1e-10f); }
        float pb = g_p1b[b];
        if (pb > 0.f) { float q = pb / S1; t -= q * logf(q + 1e-10f); }
        float pd = g_p1d[b];
        if (pd > 0.f) { float q = pd / S1; t -= q * logf(q + 1e-10f); }
    }
    __shared__ float sh[8];
    int lane = threadIdx.x & 31, wid = threadIdx.x >> 5;
    int nw = blockDim.x >> 5;
#pragma unroll
    for (int o = 16; o; o >>= 1) t += __shfl_xor_sync(0xffffffffu, t, o);
    if (lane == 0) sh[wid] = t;
    __syncthreads();
    if (wid == 0) {
        t = (lane < nw) ? sh[lane] : 0.f;
#pragma unroll
        for (int o = 4; o; o >>= 1) t += __shfl_xor_sync(0xffffffffu, t, o);
        if (lane == 0) atomicAdd(ent, t);
    }
}

// ---------------- launch ----------------
extern "C" void kernel_launch(void* const* d_in, const int* in_sizes, int n_in,
                              void* d_out, int out_size) {
    const float* pc = (const float*)d_in[0];
    const float* rb = (const float*)d_in[1];
    const float* rd = (const float*)d_in[2];
    const float* W1 = (const float*)d_in[3];
    const float* b1 = (const float*)d_in[4];
    const float* W2 = (const float*)d_in[5];
    const float* b2 = (const float*)d_in[6];
    const float* W3 = (const float*)d_in[7];
    const float* b3 = (const float*)d_in[8];
    float* out = (float*)d_out;

    int B = in_sizes[1] / NF1;          // rand_births is [B, NF1]
    if (B > BMAX) B = BMAX;

    float* euler = out + FDIM;          // output layout: [features(512) | euler(B) | entropy(1)]
    float* ent   = out + FDIM + B;

    k_init<<<1, 64>>>(ent);
    k_bp<<<1, H1>>>(W1, b1);
    k_table<<<NSEG, H2>>>(W1, b1, W2, b2);
    k_mst<<<(B + 127) / 128, 128>>>(pc, rb, rd, euler, B);
    k_diag0<<<296, 256>>>(NEDGE * B);
    k_diag1<<<296, 256>>>(W1, b1, W2, b2, rb, rd, B);
    k_feat<<<1, FDIM>>>(W3, b3, out, B);
    k_entropy<<<(B + 255) / 256, 256>>>(ent, B);
}